// round 2
// baseline (speedup 1.0000x reference)
#include <cuda_runtime.h>
#include <cstdint>
#include <math.h>

// Problem constants
#define BB   2
#define NN   2000
#define GG   100
#define HH   800
#define WW   800
#define TT   200
#define PP   66
#define NEGN 134
#define MH   28
#define MW   28

// d_out float32 layout (flattened tuple concat):
//   rois     : [0,        1600)   (B,T,4)
//   class_ids: [1600,     2000)   (B,T)
//   deltas   : [2000,     3600)   (B,T,4)
//   masks    : [3600,   317200)   (B,T,28,28)
#define BASE_ROI 0
#define BASE_CLS (BB*TT*4)
#define BASE_DLT (BASE_CLS + BB*TT)
#define BASE_MSK (BASE_DLT + BB*TT*4)

// Scratch (no device allocation allowed -> __device__ globals)
__device__ int   g_mask_mode;            // 0 = byte(bool/uint8), 1 = float32, 2 = int32
__device__ int   g_sel_ok[BB*PP];
__device__ int   g_sel_gt[BB*PP];
__device__ float g_sel_box[BB*PP*4];

// ---------------------------------------------------------------------------
// K0: detect mask storage encoding from the first 32KB of words.
// ---------------------------------------------------------------------------
__global__ void detect_mode_kernel(const void* masks) {
    __shared__ int weird, sawF;
    if (threadIdx.x == 0) { weird = 0; sawF = 0; }
    __syncthreads();
    const unsigned int* w = (const unsigned int*)masks;
    for (int i = threadIdx.x; i < 8192; i += blockDim.x) {
        unsigned int v = w[i];
        if (v == 0x3F800000u)            atomicOr(&sawF, 1);
        else if (v != 0u && v != 1u)     atomicOr(&weird, 1);
    }
    __syncthreads();
    if (threadIdx.x == 0) {
        g_mask_mode = weird ? 0 : (sawF ? 1 : 2);
    }
}

// ---------------------------------------------------------------------------
// Descending bitonic sort of 2048 uint64 keys in shared memory.
// Key = ordered_float(value) << 32 | (0xFFFFFFFF - idx)
//  -> descending value, ascending index on ties (== jax.lax.top_k order).
// ---------------------------------------------------------------------------
__device__ __forceinline__ void bitonic_desc_2048(unsigned long long* key, int tid, int nt) {
    for (int k = 2; k <= 2048; k <<= 1) {
        for (int j = k >> 1; j > 0; j >>= 1) {
            __syncthreads();
            for (int i = tid; i < 2048; i += nt) {
                int ixj = i ^ j;
                if (ixj > i) {
                    unsigned long long a = key[i], c = key[ixj];
                    bool descSeg = ((i & k) == 0);
                    if (descSeg ? (a < c) : (a > c)) { key[i] = c; key[ixj] = a; }
                }
            }
        }
    }
    __syncthreads();
}

__device__ __forceinline__ unsigned int float_ord(float f) {
    unsigned int u = __float_as_uint(f);
    return (u & 0x80000000u) ? ~u : (u | 0x80000000u);
}

// ---------------------------------------------------------------------------
// K1: per-image IoU + top-k selection + rois/class/deltas outputs.
// ---------------------------------------------------------------------------
__global__ void __launch_bounds__(256) select_kernel(
    const float* __restrict__ props,   // (B,N,4)
    const int*   __restrict__ cls,     // (B,G)
    const float* __restrict__ boxes,   // (B,G,4)
    float*       __restrict__ out)
{
    const int b = blockIdx.x;
    const int tid = threadIdx.x, nt = blockDim.x;

    __shared__ float s_gt[GG*4];
    __shared__ int   s_cls[GG];
    __shared__ float s_miou[NN];
    __shared__ float s_cmax[NN];
    __shared__ short s_asn[NN];
    __shared__ unsigned long long s_key[2048];

    for (int i = tid; i < GG*4; i += nt) s_gt[i]  = boxes[b*GG*4 + i];
    for (int i = tid; i < GG;   i += nt) s_cls[i] = cls[b*GG + i];
    __syncthreads();

    // IoU over all proposals
    for (int n = tid; n < NN; n += nt) {
        const float* p = &props[(b*NN + n)*4];
        float py1 = p[0], px1 = p[1], py2 = p[2], px2 = p[3];
        float a1 = (py2 - py1) * (px2 - px1);
        float best = -1.0f; int bi = 0; float cmax = -1.0f;
        #pragma unroll 4
        for (int g = 0; g < GG; g++) {
            float gy1 = s_gt[g*4+0], gx1 = s_gt[g*4+1];
            float gy2 = s_gt[g*4+2], gx2 = s_gt[g*4+3];
            float yy1 = fmaxf(py1, gy1), xx1 = fmaxf(px1, gx1);
            float yy2 = fminf(py2, gy2), xx2 = fminf(px2, gx2);
            float ih = fmaxf(yy2 - yy1, 0.0f);
            float iw = fmaxf(xx2 - xx1, 0.0f);
            float inter = ih * iw;
            float a2 = (gy2 - gy1) * (gx2 - gx1);
            float uni = a1 + a2 - inter;
            float iou = inter / fmaxf(uni, 1e-12f);
            bool crowd = (s_cls[g] < 0);
            float ov = crowd ? -1.0f : iou;
            if (ov > best) { best = ov; bi = g; }   // first-occurrence argmax
            float cv = crowd ? iou : -1.0f;
            if (cv > cmax) cmax = cv;
        }
        s_miou[n] = best;
        s_asn[n]  = (short)bi;
        s_cmax[n] = cmax;
    }
    __syncthreads();

    // ---- positives: top-P of where(positive, miou, -1) ----
    for (int n = tid; n < 2048; n += nt) {
        unsigned long long k = 0ull;
        if (n < NN) {
            float v = (s_miou[n] >= 0.5f) ? s_miou[n] : -1.0f;
            k = ((unsigned long long)float_ord(v) << 32) | (unsigned int)(0xFFFFFFFFu - (unsigned int)n);
        }
        s_key[n] = k;
    }
    bitonic_desc_2048(s_key, tid, nt);

    for (int i = tid; i < PP; i += nt) {
        int n = (int)(0xFFFFFFFFu - (unsigned int)s_key[i]);
        bool ok = (s_miou[n] >= 0.5f);
        int g = (int)s_asn[n];
        const float* p = &props[(b*NN + n)*4];
        float r0 = p[0], r1 = p[1], r2 = p[2], r3 = p[3];
        int oT = b*TT + i;

        out[BASE_ROI + oT*4 + 0] = ok ? r0 : 0.0f;
        out[BASE_ROI + oT*4 + 1] = ok ? r1 : 0.0f;
        out[BASE_ROI + oT*4 + 2] = ok ? r2 : 0.0f;
        out[BASE_ROI + oT*4 + 3] = ok ? r3 : 0.0f;
        out[BASE_CLS + oT] = ok ? (float)s_cls[g] : 0.0f;

        float d0=0.f, d1=0.f, d2=0.f, d3=0.f;
        if (ok) {
            float h  = r2 - r0, w = r3 - r1;
            float cy = r0 + 0.5f*h, cx = r1 + 0.5f*w;
            float gy1 = s_gt[g*4+0], gx1 = s_gt[g*4+1];
            float gy2 = s_gt[g*4+2], gx2 = s_gt[g*4+3];
            float gh = gy2 - gy1, gw = gx2 - gx1;
            float gcy = gy1 + 0.5f*gh, gcx = gx1 + 0.5f*gw;
            d0 = ((gcy - cy) / h) / 0.1f;
            d1 = ((gcx - cx) / w) / 0.1f;
            d2 = logf(gh / h) / 0.2f;
            d3 = logf(gw / w) / 0.2f;
        }
        out[BASE_DLT + oT*4 + 0] = d0;
        out[BASE_DLT + oT*4 + 1] = d1;
        out[BASE_DLT + oT*4 + 2] = d2;
        out[BASE_DLT + oT*4 + 3] = d3;

        int s = b*PP + i;
        g_sel_ok[s]      = ok ? 1 : 0;
        g_sel_gt[s]      = g;
        g_sel_box[s*4+0] = r0;
        g_sel_box[s*4+1] = r1;
        g_sel_box[s*4+2] = r2;
        g_sel_box[s*4+3] = r3;
    }
    __syncthreads();

    // ---- negatives: top-NEG of where(negative, miou, -1) ----
    for (int n = tid; n < 2048; n += nt) {
        unsigned long long k = 0ull;
        if (n < NN) {
            bool neg = (s_miou[n] < 0.5f) && (s_cmax[n] < 0.001f);
            float v = neg ? s_miou[n] : -1.0f;
            k = ((unsigned long long)float_ord(v) << 32) | (unsigned int)(0xFFFFFFFFu - (unsigned int)n);
        }
        s_key[n] = k;
    }
    bitonic_desc_2048(s_key, tid, nt);

    for (int i = tid; i < NEGN; i += nt) {
        int n = (int)(0xFFFFFFFFu - (unsigned int)s_key[i]);
        bool ok = (s_miou[n] < 0.5f) && (s_cmax[n] < 0.001f);
        const float* p = &props[(b*NN + n)*4];
        int oT = b*TT + PP + i;
        out[BASE_ROI + oT*4 + 0] = ok ? p[0] : 0.0f;
        out[BASE_ROI + oT*4 + 1] = ok ? p[1] : 0.0f;
        out[BASE_ROI + oT*4 + 2] = ok ? p[2] : 0.0f;
        out[BASE_ROI + oT*4 + 3] = ok ? p[3] : 0.0f;
        out[BASE_CLS + oT] = 0.0f;
        out[BASE_DLT + oT*4 + 0] = 0.0f;
        out[BASE_DLT + oT*4 + 1] = 0.0f;
        out[BASE_DLT + oT*4 + 2] = 0.0f;
        out[BASE_DLT + oT*4 + 3] = 0.0f;
    }
}

// ---------------------------------------------------------------------------
// K2: mask crop-resize. One block per (b,t).
// All float math uses explicit round-to-nearest intrinsics (NO fma
// contraction) to bit-match XLA's unfused mul/add sequence, since the
// round() threshold at 0.5 makes pixel values knife-edge sensitive.
// ---------------------------------------------------------------------------
__device__ __forceinline__ float read_mask(const void* m, int mode, int b, int y, int x, int g) {
    size_t idx = (((size_t)b*HH + y)*WW + x)*GG + g;
    if (mode == 0) return ((const unsigned char*)m)[idx] ? 1.0f : 0.0f;
    if (mode == 1) return ((const float*)m)[idx];
    return (float)((const int*)m)[idx];
}

__global__ void __launch_bounds__(256) mask_kernel(const void* __restrict__ masks,
                                                   float* __restrict__ out)
{
    const int bt = blockIdx.x;
    const int b = bt / TT, t = bt % TT;
    float* mout = out + BASE_MSK + (size_t)bt * (MH*MW);

    if (t >= PP || !g_sel_ok[b*PP + t]) {
        for (int i = threadIdx.x; i < MH*MW; i += blockDim.x) mout[i] = 0.0f;
        return;
    }
    const int s = b*PP + t;
    const int g = g_sel_gt[s];
    const float by1 = g_sel_box[s*4+0], bx1 = g_sel_box[s*4+1];
    const float by2 = g_sel_box[s*4+2], bx2 = g_sel_box[s*4+3];
    const int mode = g_mask_mode;

    // Match XLA op order exactly: dy = by2 - by1 (single rn sub)
    const float dy = __fsub_rn(by2, by1);
    const float dx = __fsub_rn(bx2, bx1);
    const float baseY = __fmul_rn(by1, (float)(HH-1));
    const float baseX = __fmul_rn(bx1, (float)(WW-1));

    for (int i = threadIdx.x; i < MH*MW; i += blockDim.x) {
        int py = i / MW, px = i % MW;
        // ys = by1*(H-1) + ((py/(MH-1)) * (by2-by1)) * (H-1)   [all separate rn ops]
        float ty = __fdiv_rn((float)py, (float)(MH-1));
        float ys = __fadd_rn(baseY, __fmul_rn(__fmul_rn(ty, dy), (float)(HH-1)));
        float tx = __fdiv_rn((float)px, (float)(MW-1));
        float xs = __fadd_rn(baseX, __fmul_rn(__fmul_rn(tx, dx), (float)(WW-1)));

        float y0f = floorf(ys), x0f = floorf(xs);
        float wy = __fsub_rn(ys, y0f);
        float wx = __fsub_rn(xs, x0f);
        int y0 = min(max((int)y0f, 0), HH-1);
        int y1 = min(y0 + 1, HH-1);
        int x0 = min(max((int)x0f, 0), WW-1);
        int x1 = min(x0 + 1, WW-1);

        float v00 = read_mask(masks, mode, b, y0, x0, g);
        float v01 = read_mask(masks, mode, b, y0, x1, g);
        float v10 = read_mask(masks, mode, b, y1, x0, g);
        float v11 = read_mask(masks, mode, b, y1, x1, g);

        float omwx = __fsub_rn(1.0f, wx);
        float omwy = __fsub_rn(1.0f, wy);
        // top = v00*(1-wx) + v01*wx  (unfused)
        float top = __fadd_rn(__fmul_rn(v00, omwx), __fmul_rn(v01, wx));
        float bot = __fadd_rn(__fmul_rn(v10, omwx), __fmul_rn(v11, wx));
        float v   = __fadd_rn(__fmul_rn(top, omwy), __fmul_rn(bot, wy));
        mout[i] = rintf(v);   // jnp.round = half-to-even
    }
}

// ---------------------------------------------------------------------------
extern "C" void kernel_launch(void* const* d_in, const int* in_sizes, int n_in,
                              void* d_out, int out_size)
{
    const float* props = (const float*)d_in[0];   // (B,N,4)
    const int*   cls   = (const int*)  d_in[1];   // (B,G)
    const float* boxes = (const float*)d_in[2];   // (B,G,4)
    const void*  masks = d_in[3];                 // (B,H,W,G), dtype detected on device

    float* out = (float*)d_out;

    detect_mode_kernel<<<1, 256>>>(masks);
    select_kernel<<<BB, 256>>>(props, cls, boxes, out);
    mask_kernel<<<BB*TT, 256>>>(masks, out);
}

// round 3
// speedup vs baseline: 2.6320x; 2.6320x over previous
#include <cuda_runtime.h>
#include <cstdint>
#include <math.h>

// Problem constants
#define BB   2
#define NN   2000
#define GG   100
#define HH   800
#define WW   800
#define TT   200
#define PP   66
#define NEGN 134
#define MH   28
#define MW   28

// d_out float32 layout (flattened tuple concat):
#define BASE_ROI 0
#define BASE_CLS (BB*TT*4)
#define BASE_DLT (BASE_CLS + BB*TT)
#define BASE_MSK (BASE_DLT + BB*TT*4)

// Scratch (no device allocation allowed -> __device__ globals)
__device__ int   g_mask_mode;            // 0 = byte(bool/uint8), 1 = float32, 2 = int32
__device__ int   g_sel_ok[BB*PP];
__device__ int   g_sel_gt[BB*PP];
__device__ float g_sel_box[BB*PP*4];

__device__ __forceinline__ unsigned int float_ord(float f) {
    unsigned int u = __float_as_uint(f);
    return (u & 0x80000000u) ? ~u : (u | 0x80000000u);
}

// ---------------------------------------------------------------------------
// Hybrid register/shfl/shared bitonic sort, 2048 uint64 keys, DESCENDING.
// 1024 threads; thread t owns elements t (r0) and t+1024 (r1).
// j<32  : warp shfl, no barrier (45 passes)
// j>=32 : shared exchange, both partners compute keep (20 passes)
// j=1024: in-thread pair (1 pass)
// On exit: s[0..2047] holds the sorted keys.
// ---------------------------------------------------------------------------
__device__ __forceinline__ unsigned long long umax64(unsigned long long a, unsigned long long b) { return a > b ? a : b; }
__device__ __forceinline__ unsigned long long umin64(unsigned long long a, unsigned long long b) { return a > b ? b : a; }

__device__ void sort2048_desc(unsigned long long r0, unsigned long long r1,
                              unsigned long long* s, int t)
{
    for (int k = 2; k <= 2048; k <<= 1) {
        for (int j = k >> 1; j > 0; j >>= 1) {
            if (j == 1024) {
                // pair (t, t+1024), segment descending (t & 2048 == 0)
                unsigned long long hi = umax64(r0, r1);
                unsigned long long lo = umin64(r0, r1);
                r0 = hi; r1 = lo;
            } else if (j >= 32) {
                __syncthreads();
                s[t] = r0; s[t + 1024] = r1;
                __syncthreads();
                unsigned long long p0 = s[t ^ j];
                unsigned long long p1 = s[(t ^ j) + 1024];
                bool up = ((t & j) == 0);
                bool d0 = ((t & k) == 0);
                bool d1 = (((t + 1024) & k) == 0);
                r0 = (up == d0) ? umax64(r0, p0) : umin64(r0, p0);
                r1 = (up == d1) ? umax64(r1, p1) : umin64(r1, p1);
            } else {
                unsigned long long p0 = __shfl_xor_sync(0xFFFFFFFFu, r0, j);
                unsigned long long p1 = __shfl_xor_sync(0xFFFFFFFFu, r1, j);
                bool up = ((t & j) == 0);
                bool d0 = ((t & k) == 0);
                bool d1 = (((t + 1024) & k) == 0);
                r0 = (up == d0) ? umax64(r0, p0) : umin64(r0, p0);
                r1 = (up == d1) ? umax64(r1, p1) : umin64(r1, p1);
            }
        }
    }
    __syncthreads();
    s[t] = r0; s[t + 1024] = r1;
    __syncthreads();
}

// ---------------------------------------------------------------------------
// K1: blocks 0..3 -> (image b = blk>>1, role = blk&1: 0=pos, 1=neg)
//     block 4     -> mask dtype detection (one warp, ballot-reduced)
// ---------------------------------------------------------------------------
__global__ void __launch_bounds__(1024, 1) select_kernel(
    const float* __restrict__ props,   // (B,N,4)
    const int*   __restrict__ cls,     // (B,G)
    const float* __restrict__ boxes,   // (B,G,4)
    const void*  __restrict__ masks,
    float*       __restrict__ out)
{
    // ---- block 4: dtype detection ----
    if (blockIdx.x == 4) {
        if (threadIdx.x < 32) {
            const uint4* w = (const uint4*)masks;
            bool weird = false, sawF = false;
            for (int i = threadIdx.x; i < 512; i += 32) {   // 8KB sample
                uint4 v = w[i];
                #define CHK(x) { unsigned int u = (x); \
                    if (u == 0x3F800000u) sawF = true; \
                    else if (u != 0u && u != 1u) weird = true; }
                CHK(v.x) CHK(v.y) CHK(v.z) CHK(v.w)
                #undef CHK
            }
            weird = __any_sync(0xFFFFFFFFu, weird);
            sawF  = __any_sync(0xFFFFFFFFu, sawF);
            if (threadIdx.x == 0) g_mask_mode = weird ? 0 : (sawF ? 1 : 2);
        }
        return;
    }

    const int b    = blockIdx.x >> 1;
    const int role = blockIdx.x & 1;          // 0 = positives, 1 = negatives
    const int t    = threadIdx.x;

    __shared__ float s_gt[GG*4];
    __shared__ int   s_cls[GG];
    __shared__ float s_miou[NN];
    __shared__ float s_cmax[NN];
    __shared__ short s_asn[NN];
    __shared__ unsigned long long s_key[2048];

    for (int i = t; i < GG*4; i += 1024) s_gt[i]  = boxes[b*GG*4 + i];
    for (int i = t; i < GG;   i += 1024) s_cls[i] = cls[b*GG + i];
    __syncthreads();

    // IoU over all proposals (2 iterations/thread)
    for (int n = t; n < NN; n += 1024) {
        const float* p = &props[(b*NN + n)*4];
        float py1 = p[0], px1 = p[1], py2 = p[2], px2 = p[3];
        float a1 = (py2 - py1) * (px2 - px1);
        float best = -1.0f; int bi = 0; float cmax = -1.0f;
        #pragma unroll 4
        for (int g = 0; g < GG; g++) {
            float gy1 = s_gt[g*4+0], gx1 = s_gt[g*4+1];
            float gy2 = s_gt[g*4+2], gx2 = s_gt[g*4+3];
            float yy1 = fmaxf(py1, gy1), xx1 = fmaxf(px1, gx1);
            float yy2 = fminf(py2, gy2), xx2 = fminf(px2, gx2);
            float ih = fmaxf(yy2 - yy1, 0.0f);
            float iw = fmaxf(xx2 - xx1, 0.0f);
            float inter = ih * iw;
            float a2 = (gy2 - gy1) * (gx2 - gx1);
            float uni = a1 + a2 - inter;
            float iou = inter / fmaxf(uni, 1e-12f);
            bool crowd = (s_cls[g] < 0);
            float ov = crowd ? -1.0f : iou;
            if (ov > best) { best = ov; bi = g; }   // first-occurrence argmax
            float cv = crowd ? iou : -1.0f;
            if (cv > cmax) cmax = cv;
        }
        s_miou[n] = best;
        s_asn[n]  = (short)bi;
        s_cmax[n] = cmax;
    }
    __syncthreads();

    // Build keys in registers: descending value, ascending index on ties
    auto make_key = [&](int n) -> unsigned long long {
        if (n >= NN) return 0ull;
        float v;
        if (role == 0) {
            v = (s_miou[n] >= 0.5f) ? s_miou[n] : -1.0f;
        } else {
            bool neg = (s_miou[n] < 0.5f) && (s_cmax[n] < 0.001f);
            v = neg ? s_miou[n] : -1.0f;
        }
        return ((unsigned long long)float_ord(v) << 32) |
               (unsigned int)(0xFFFFFFFFu - (unsigned int)n);
    };
    unsigned long long r0 = make_key(t);
    unsigned long long r1 = make_key(t + 1024);

    sort2048_desc(r0, r1, s_key, t);

    if (role == 0) {
        // ---- positives: rois / class_ids / deltas / selection scratch ----
        if (t < PP) {
            int i = t;
            int n = (int)(0xFFFFFFFFu - (unsigned int)s_key[i]);
            bool ok = (s_miou[n] >= 0.5f);
            int g = (int)s_asn[n];
            const float* p = &props[(b*NN + n)*4];
            float q0 = p[0], q1 = p[1], q2 = p[2], q3 = p[3];
            int oT = b*TT + i;

            out[BASE_ROI + oT*4 + 0] = ok ? q0 : 0.0f;
            out[BASE_ROI + oT*4 + 1] = ok ? q1 : 0.0f;
            out[BASE_ROI + oT*4 + 2] = ok ? q2 : 0.0f;
            out[BASE_ROI + oT*4 + 3] = ok ? q3 : 0.0f;
            out[BASE_CLS + oT] = ok ? (float)s_cls[g] : 0.0f;

            float d0=0.f, d1=0.f, d2=0.f, d3=0.f;
            if (ok) {
                float h  = q2 - q0, w = q3 - q1;
                float cy = q0 + 0.5f*h, cx = q1 + 0.5f*w;
                float gy1 = s_gt[g*4+0], gx1 = s_gt[g*4+1];
                float gy2 = s_gt[g*4+2], gx2 = s_gt[g*4+3];
                float gh = gy2 - gy1, gw = gx2 - gx1;
                float gcy = gy1 + 0.5f*gh, gcx = gx1 + 0.5f*gw;
                d0 = ((gcy - cy) / h) / 0.1f;
                d1 = ((gcx - cx) / w) / 0.1f;
                d2 = logf(gh / h) / 0.2f;
                d3 = logf(gw / w) / 0.2f;
            }
            out[BASE_DLT + oT*4 + 0] = d0;
            out[BASE_DLT + oT*4 + 1] = d1;
            out[BASE_DLT + oT*4 + 2] = d2;
            out[BASE_DLT + oT*4 + 3] = d3;

            int s = b*PP + i;
            g_sel_ok[s]      = ok ? 1 : 0;
            g_sel_gt[s]      = g;
            g_sel_box[s*4+0] = q0;
            g_sel_box[s*4+1] = q1;
            g_sel_box[s*4+2] = q2;
            g_sel_box[s*4+3] = q3;
        }
    } else {
        // ---- negatives ----
        if (t < NEGN) {
            int i = t;
            int n = (int)(0xFFFFFFFFu - (unsigned int)s_key[i]);
            bool ok = (s_miou[n] < 0.5f) && (s_cmax[n] < 0.001f);
            const float* p = &props[(b*NN + n)*4];
            int oT = b*TT + PP + i;
            out[BASE_ROI + oT*4 + 0] = ok ? p[0] : 0.0f;
            out[BASE_ROI + oT*4 + 1] = ok ? p[1] : 0.0f;
            out[BASE_ROI + oT*4 + 2] = ok ? p[2] : 0.0f;
            out[BASE_ROI + oT*4 + 3] = ok ? p[3] : 0.0f;
            out[BASE_CLS + oT] = 0.0f;
            out[BASE_DLT + oT*4 + 0] = 0.0f;
            out[BASE_DLT + oT*4 + 1] = 0.0f;
            out[BASE_DLT + oT*4 + 2] = 0.0f;
            out[BASE_DLT + oT*4 + 3] = 0.0f;
        }
    }
}

// ---------------------------------------------------------------------------
// K2: mask crop-resize. One block per (b,t).
// All float math via explicit rn intrinsics (no FMA contraction) to bit-match
// XLA's unfused mul/add sequence around the round() 0.5 knife edge.
// (VALIDATED bit-path — do not change the arithmetic.)
// ---------------------------------------------------------------------------
__device__ __forceinline__ float read_mask(const void* m, int mode, int b, int y, int x, int g) {
    size_t idx = (((size_t)b*HH + y)*WW + x)*GG + g;
    if (mode == 0) return ((const unsigned char*)m)[idx] ? 1.0f : 0.0f;
    if (mode == 1) return ((const float*)m)[idx];
    return (float)((const int*)m)[idx];
}

__global__ void __launch_bounds__(256) mask_kernel(const void* __restrict__ masks,
                                                   float* __restrict__ out)
{
    const int bt = blockIdx.x;
    const int b = bt / TT, t = bt % TT;
    float* mout = out + BASE_MSK + (size_t)bt * (MH*MW);

    if (t >= PP || !g_sel_ok[b*PP + t]) {
        for (int i = threadIdx.x; i < MH*MW; i += blockDim.x) mout[i] = 0.0f;
        return;
    }
    const int s = b*PP + t;
    const int g = g_sel_gt[s];
    const float by1 = g_sel_box[s*4+0], bx1 = g_sel_box[s*4+1];
    const float by2 = g_sel_box[s*4+2], bx2 = g_sel_box[s*4+3];
    const int mode = g_mask_mode;

    const float dy = __fsub_rn(by2, by1);
    const float dx = __fsub_rn(bx2, bx1);
    const float baseY = __fmul_rn(by1, (float)(HH-1));
    const float baseX = __fmul_rn(bx1, (float)(WW-1));

    for (int i = threadIdx.x; i < MH*MW; i += blockDim.x) {
        int py = i / MW, px = i % MW;
        float ty = __fdiv_rn((float)py, (float)(MH-1));
        float ys = __fadd_rn(baseY, __fmul_rn(__fmul_rn(ty, dy), (float)(HH-1)));
        float tx = __fdiv_rn((float)px, (float)(MW-1));
        float xs = __fadd_rn(baseX, __fmul_rn(__fmul_rn(tx, dx), (float)(WW-1)));

        float y0f = floorf(ys), x0f = floorf(xs);
        float wy = __fsub_rn(ys, y0f);
        float wx = __fsub_rn(xs, x0f);
        int y0 = min(max((int)y0f, 0), HH-1);
        int y1 = min(y0 + 1, HH-1);
        int x0 = min(max((int)x0f, 0), WW-1);
        int x1 = min(x0 + 1, WW-1);

        float v00 = read_mask(masks, mode, b, y0, x0, g);
        float v01 = read_mask(masks, mode, b, y0, x1, g);
        float v10 = read_mask(masks, mode, b, y1, x0, g);
        float v11 = read_mask(masks, mode, b, y1, x1, g);

        float omwx = __fsub_rn(1.0f, wx);
        float omwy = __fsub_rn(1.0f, wy);
        float top = __fadd_rn(__fmul_rn(v00, omwx), __fmul_rn(v01, wx));
        float bot = __fadd_rn(__fmul_rn(v10, omwx), __fmul_rn(v11, wx));
        float v   = __fadd_rn(__fmul_rn(top, omwy), __fmul_rn(bot, wy));
        mout[i] = rintf(v);   // jnp.round = half-to-even
    }
}

// ---------------------------------------------------------------------------
extern "C" void kernel_launch(void* const* d_in, const int* in_sizes, int n_in,
                              void* d_out, int out_size)
{
    const float* props = (const float*)d_in[0];   // (B,N,4)
    const int*   cls   = (const int*)  d_in[1];   // (B,G)
    const float* boxes = (const float*)d_in[2];   // (B,G,4)
    const void*  masks = d_in[3];                 // (B,H,W,G)

    float* out = (float*)d_out;

    select_kernel<<<5, 1024>>>(props, cls, boxes, masks, out);
    mask_kernel<<<BB*TT, 256>>>(masks, out);
}

// round 4
// speedup vs baseline: 7.2758x; 2.7643x over previous
#include <cuda_runtime.h>
#include <cstdint>
#include <math.h>

// Problem constants
#define BB   2
#define NN   2000
#define GG   100
#define HH   800
#define WW   800
#define TT   200
#define PP   66
#define NEGN 134
#define MH   28
#define MW   28

// d_out float32 layout (flattened tuple concat):
#define BASE_ROI 0
#define BASE_CLS (BB*TT*4)
#define BASE_DLT (BASE_CLS + BB*TT)
#define BASE_MSK (BASE_DLT + BB*TT*4)

// Scratch (no device allocation allowed -> __device__ globals)
__device__ int   g_mask_mode;            // 0 = byte(bool/uint8), 1 = float32, 2 = int32
__device__ int   g_sel_ok[BB*PP];
__device__ int   g_sel_gt[BB*PP];
__device__ float g_sel_box[BB*PP*4];
__device__ float g_miou[BB*NN];
__device__ float g_cmax[BB*NN];
__device__ int   g_asn [BB*NN];

__device__ __forceinline__ unsigned int float_ord(float f) {
    unsigned int u = __float_as_uint(f);
    return (u & 0x80000000u) ? ~u : (u | 0x80000000u);
}
__device__ __forceinline__ float ord_to_float(unsigned int k) {
    unsigned int u = (k & 0x80000000u) ? (k ^ 0x80000000u) : ~k;
    return __uint_as_float(u);
}

__device__ __forceinline__ unsigned long long umax64(unsigned long long a, unsigned long long b) { return a > b ? a : b; }
__device__ __forceinline__ unsigned long long umin64(unsigned long long a, unsigned long long b) { return a > b ? b : a; }

// ---------------------------------------------------------------------------
// Kernel A: IoU, warp-per-proposal, lanes over GT boxes.
//   grid = (250, BB+1); block = 256 (8 warps = 8 proposals).
//   blockIdx.y == BB, blockIdx.x == 0 -> mask dtype detection.
// Produces per-(b,n): miou (crowd-masked max IoU), first-occurrence argmax,
// crowd-max. Bit-identical to the sequential scan: exact-equal IoUs map to
// identical packed keys; tie resolves to min g via ~g in low bits.
// ---------------------------------------------------------------------------
__global__ void __launch_bounds__(256) iou_kernel(
    const float* __restrict__ props,   // (B,N,4)
    const int*   __restrict__ cls,     // (B,G)
    const float* __restrict__ boxes,   // (B,G,4)
    const void*  __restrict__ masks)
{
    if (blockIdx.y == BB) {
        if (blockIdx.x == 0 && threadIdx.x < 32) {
            const uint4* w = (const uint4*)masks;
            bool weird = false, sawF = false;
            for (int i = threadIdx.x; i < 512; i += 32) {   // 8KB sample
                uint4 v = w[i];
                #define CHK(x) { unsigned int u = (x); \
                    if (u == 0x3F800000u) sawF = true; \
                    else if (u != 0u && u != 1u) weird = true; }
                CHK(v.x) CHK(v.y) CHK(v.z) CHK(v.w)
                #undef CHK
            }
            weird = __any_sync(0xFFFFFFFFu, weird);
            sawF  = __any_sync(0xFFFFFFFFu, sawF);
            if (threadIdx.x == 0) g_mask_mode = weird ? 0 : (sawF ? 1 : 2);
        }
        return;
    }

    const int b = blockIdx.y;
    const int t = threadIdx.x;
    const int lane = t & 31, w = t >> 5;
    const int n = blockIdx.x * 8 + w;          // 250*8 = 2000

    __shared__ float s_gt[GG*4];
    __shared__ int   s_cls[GG];
    for (int i = t; i < GG*4; i += 256) s_gt[i]  = boxes[b*GG*4 + i];
    for (int i = t; i < GG;   i += 256) s_cls[i] = cls[b*GG + i];
    __syncthreads();

    const float4 pb = ((const float4*)props)[b*NN + n];
    const float py1 = pb.x, px1 = pb.y, py2 = pb.z, px2 = pb.w;
    const float a1 = (py2 - py1) * (px2 - px1);

    unsigned long long bestkey = 0ull;
    float cmax = -1.0f;
    for (int g = lane; g < GG; g += 32) {
        float gy1 = s_gt[g*4+0], gx1 = s_gt[g*4+1];
        float gy2 = s_gt[g*4+2], gx2 = s_gt[g*4+3];
        float yy1 = fmaxf(py1, gy1), xx1 = fmaxf(px1, gx1);
        float yy2 = fminf(py2, gy2), xx2 = fminf(px2, gx2);
        float ih = fmaxf(yy2 - yy1, 0.0f);
        float iw = fmaxf(xx2 - xx1, 0.0f);
        float inter = ih * iw;
        float a2 = (gy2 - gy1) * (gx2 - gx1);
        float uni = a1 + a2 - inter;
        float iou = inter / fmaxf(uni, 1e-12f);
        bool crowd = (s_cls[g] < 0);
        float ov = crowd ? -1.0f : iou;
        unsigned long long key = ((unsigned long long)float_ord(ov) << 32) |
                                 (unsigned int)(0xFFFFFFFFu - (unsigned int)g);
        bestkey = umax64(bestkey, key);
        cmax = fmaxf(cmax, crowd ? iou : -1.0f);
    }
    #pragma unroll
    for (int o = 16; o > 0; o >>= 1) {
        bestkey = umax64(bestkey, __shfl_xor_sync(0xFFFFFFFFu, bestkey, o));
        cmax    = fmaxf(cmax,     __shfl_xor_sync(0xFFFFFFFFu, cmax,    o));
    }
    if (lane == 0) {
        g_miou[b*NN + n] = ord_to_float((unsigned int)(bestkey >> 32));
        g_asn [b*NN + n] = (int)(0xFFFFFFFFu - (unsigned int)(bestkey & 0xFFFFFFFFull));
        g_cmax[b*NN + n] = cmax;
    }
}

// ---------------------------------------------------------------------------
// Hybrid register/shfl/shared bitonic sort, 2048 uint64 keys, DESCENDING.
// ---------------------------------------------------------------------------
__device__ void sort2048_desc(unsigned long long r0, unsigned long long r1,
                              unsigned long long* s, int t)
{
    for (int k = 2; k <= 2048; k <<= 1) {
        for (int j = k >> 1; j > 0; j >>= 1) {
            if (j == 1024) {
                unsigned long long hi = umax64(r0, r1);
                unsigned long long lo = umin64(r0, r1);
                r0 = hi; r1 = lo;
            } else if (j >= 32) {
                __syncthreads();
                s[t] = r0; s[t + 1024] = r1;
                __syncthreads();
                unsigned long long p0 = s[t ^ j];
                unsigned long long p1 = s[(t ^ j) + 1024];
                bool up = ((t & j) == 0);
                bool d0 = ((t & k) == 0);
                bool d1 = (((t + 1024) & k) == 0);
                r0 = (up == d0) ? umax64(r0, p0) : umin64(r0, p0);
                r1 = (up == d1) ? umax64(r1, p1) : umin64(r1, p1);
            } else {
                unsigned long long p0 = __shfl_xor_sync(0xFFFFFFFFu, r0, j);
                unsigned long long p1 = __shfl_xor_sync(0xFFFFFFFFu, r1, j);
                bool up = ((t & j) == 0);
                bool d0 = ((t & k) == 0);
                bool d1 = (((t + 1024) & k) == 0);
                r0 = (up == d0) ? umax64(r0, p0) : umin64(r0, p0);
                r1 = (up == d1) ? umax64(r1, p1) : umin64(r1, p1);
            }
        }
    }
    __syncthreads();
    s[t] = r0; s[t + 1024] = r1;
    __syncthreads();
}

// ---------------------------------------------------------------------------
// Kernel B: top-k select + output writes.
//   blocks 0..3: (image b = blk>>1, role = blk&1: 0=pos, 1=neg)
// ---------------------------------------------------------------------------
__global__ void __launch_bounds__(1024, 1) select_kernel(
    const float* __restrict__ props,   // (B,N,4)
    const int*   __restrict__ cls,     // (B,G)
    const float* __restrict__ boxes,   // (B,G,4)
    float*       __restrict__ out)
{
    const int b    = blockIdx.x >> 1;
    const int role = blockIdx.x & 1;          // 0 = positives, 1 = negatives
    const int t    = threadIdx.x;

    __shared__ float s_gt[GG*4];
    __shared__ int   s_cls[GG];
    __shared__ float s_miou[NN];
    __shared__ float s_cmax[NN];
    __shared__ unsigned long long s_key[2048];

    for (int i = t; i < GG*4; i += 1024) s_gt[i]  = boxes[b*GG*4 + i];
    for (int i = t; i < GG;   i += 1024) s_cls[i] = cls[b*GG + i];
    for (int i = t; i < NN;   i += 1024) {
        s_miou[i] = g_miou[b*NN + i];
        s_cmax[i] = g_cmax[b*NN + i];
    }
    __syncthreads();

    auto make_key = [&](int n) -> unsigned long long {
        if (n >= NN) return 0ull;
        float v;
        if (role == 0) {
            v = (s_miou[n] >= 0.5f) ? s_miou[n] : -1.0f;
        } else {
            bool neg = (s_miou[n] < 0.5f) && (s_cmax[n] < 0.001f);
            v = neg ? s_miou[n] : -1.0f;
        }
        return ((unsigned long long)float_ord(v) << 32) |
               (unsigned int)(0xFFFFFFFFu - (unsigned int)n);
    };
    unsigned long long r0 = make_key(t);
    unsigned long long r1 = make_key(t + 1024);

    sort2048_desc(r0, r1, s_key, t);

    if (role == 0) {
        if (t < PP) {
            int i = t;
            int n = (int)(0xFFFFFFFFu - (unsigned int)s_key[i]);
            bool ok = (s_miou[n] >= 0.5f);
            int g = g_asn[b*NN + n];
            const float* p = &props[(b*NN + n)*4];
            float q0 = p[0], q1 = p[1], q2 = p[2], q3 = p[3];
            int oT = b*TT + i;

            out[BASE_ROI + oT*4 + 0] = ok ? q0 : 0.0f;
            out[BASE_ROI + oT*4 + 1] = ok ? q1 : 0.0f;
            out[BASE_ROI + oT*4 + 2] = ok ? q2 : 0.0f;
            out[BASE_ROI + oT*4 + 3] = ok ? q3 : 0.0f;
            out[BASE_CLS + oT] = ok ? (float)s_cls[g] : 0.0f;

            float d0=0.f, d1=0.f, d2=0.f, d3=0.f;
            if (ok) {
                float h  = q2 - q0, w = q3 - q1;
                float cy = q0 + 0.5f*h, cx = q1 + 0.5f*w;
                float gy1 = s_gt[g*4+0], gx1 = s_gt[g*4+1];
                float gy2 = s_gt[g*4+2], gx2 = s_gt[g*4+3];
                float gh = gy2 - gy1, gw = gx2 - gx1;
                float gcy = gy1 + 0.5f*gh, gcx = gx1 + 0.5f*gw;
                d0 = ((gcy - cy) / h) / 0.1f;
                d1 = ((gcx - cx) / w) / 0.1f;
                d2 = logf(gh / h) / 0.2f;
                d3 = logf(gw / w) / 0.2f;
            }
            out[BASE_DLT + oT*4 + 0] = d0;
            out[BASE_DLT + oT*4 + 1] = d1;
            out[BASE_DLT + oT*4 + 2] = d2;
            out[BASE_DLT + oT*4 + 3] = d3;

            int s = b*PP + i;
            g_sel_ok[s]      = ok ? 1 : 0;
            g_sel_gt[s]      = g;
            g_sel_box[s*4+0] = q0;
            g_sel_box[s*4+1] = q1;
            g_sel_box[s*4+2] = q2;
            g_sel_box[s*4+3] = q3;
        }
    } else {
        if (t < NEGN) {
            int i = t;
            int n = (int)(0xFFFFFFFFu - (unsigned int)s_key[i]);
            bool ok = (s_miou[n] < 0.5f) && (s_cmax[n] < 0.001f);
            const float* p = &props[(b*NN + n)*4];
            int oT = b*TT + PP + i;
            out[BASE_ROI + oT*4 + 0] = ok ? p[0] : 0.0f;
            out[BASE_ROI + oT*4 + 1] = ok ? p[1] : 0.0f;
            out[BASE_ROI + oT*4 + 2] = ok ? p[2] : 0.0f;
            out[BASE_ROI + oT*4 + 3] = ok ? p[3] : 0.0f;
            out[BASE_CLS + oT] = 0.0f;
            out[BASE_DLT + oT*4 + 0] = 0.0f;
            out[BASE_DLT + oT*4 + 1] = 0.0f;
            out[BASE_DLT + oT*4 + 2] = 0.0f;
            out[BASE_DLT + oT*4 + 3] = 0.0f;
        }
    }
}

// ---------------------------------------------------------------------------
// Kernel C: mask crop-resize. One block per (b,t), one THREAD per pixel
// (784 threads) for max memory-level parallelism on the scattered gathers.
// All float math via explicit rn intrinsics (no FMA contraction) to bit-match
// XLA's unfused mul/add sequence around the round() 0.5 knife edge.
// (VALIDATED bit-path — do not change the arithmetic.)
// ---------------------------------------------------------------------------
__device__ __forceinline__ float read_mask(const void* m, int mode, int b, int y, int x, int g) {
    size_t idx = (((size_t)b*HH + y)*WW + x)*GG + g;
    if (mode == 0) return ((const unsigned char*)m)[idx] ? 1.0f : 0.0f;
    if (mode == 1) return ((const float*)m)[idx];
    return (float)((const int*)m)[idx];
}

__global__ void __launch_bounds__(784) mask_kernel(const void* __restrict__ masks,
                                                   float* __restrict__ out)
{
    const int bt = blockIdx.x;
    const int b = bt / TT, t = bt % TT;
    float* mout = out + BASE_MSK + (size_t)bt * (MH*MW);
    const int i = threadIdx.x;           // 0..783, one pixel each

    if (t >= PP || !g_sel_ok[b*PP + t]) {
        mout[i] = 0.0f;
        return;
    }
    const int s = b*PP + t;
    const int g = g_sel_gt[s];
    const float by1 = g_sel_box[s*4+0], bx1 = g_sel_box[s*4+1];
    const float by2 = g_sel_box[s*4+2], bx2 = g_sel_box[s*4+3];
    const int mode = g_mask_mode;

    const float dy = __fsub_rn(by2, by1);
    const float dx = __fsub_rn(bx2, bx1);
    const float baseY = __fmul_rn(by1, (float)(HH-1));
    const float baseX = __fmul_rn(bx1, (float)(WW-1));

    int py = i / MW, px = i % MW;
    float ty = __fdiv_rn((float)py, (float)(MH-1));
    float ys = __fadd_rn(baseY, __fmul_rn(__fmul_rn(ty, dy), (float)(HH-1)));
    float tx = __fdiv_rn((float)px, (float)(MW-1));
    float xs = __fadd_rn(baseX, __fmul_rn(__fmul_rn(tx, dx), (float)(WW-1)));

    float y0f = floorf(ys), x0f = floorf(xs);
    float wy = __fsub_rn(ys, y0f);
    float wx = __fsub_rn(xs, x0f);
    int y0 = min(max((int)y0f, 0), HH-1);
    int y1 = min(y0 + 1, HH-1);
    int x0 = min(max((int)x0f, 0), WW-1);
    int x1 = min(x0 + 1, WW-1);

    float v00 = read_mask(masks, mode, b, y0, x0, g);
    float v01 = read_mask(masks, mode, b, y0, x1, g);
    float v10 = read_mask(masks, mode, b, y1, x0, g);
    float v11 = read_mask(masks, mode, b, y1, x1, g);

    float omwx = __fsub_rn(1.0f, wx);
    float omwy = __fsub_rn(1.0f, wy);
    float top = __fadd_rn(__fmul_rn(v00, omwx), __fmul_rn(v01, wx));
    float bot = __fadd_rn(__fmul_rn(v10, omwx), __fmul_rn(v11, wx));
    float v   = __fadd_rn(__fmul_rn(top, omwy), __fmul_rn(bot, wy));
    mout[i] = rintf(v);   // jnp.round = half-to-even
}

// ---------------------------------------------------------------------------
extern "C" void kernel_launch(void* const* d_in, const int* in_sizes, int n_in,
                              void* d_out, int out_size)
{
    const float* props = (const float*)d_in[0];   // (B,N,4)
    const int*   cls   = (const int*)  d_in[1];   // (B,G)
    const float* boxes = (const float*)d_in[2];   // (B,G,4)
    const void*  masks = d_in[3];                 // (B,H,W,G)

    float* out = (float*)d_out;

    dim3 gridA(250, BB + 1);
    iou_kernel<<<gridA, 256>>>(props, cls, boxes, masks);
    select_kernel<<<4, 1024>>>(props, cls, boxes, out);
    mask_kernel<<<BB*TT, 784>>>(masks, out);
}

// round 5
// speedup vs baseline: 9.0024x; 1.2373x over previous
#include <cuda_runtime.h>
#include <cstdint>
#include <math.h>

// Problem constants
#define BB   2
#define NN   2000
#define GG   100
#define HH   800
#define WW   800
#define TT   200
#define PP   66
#define NEGN 134
#define MH   28
#define MW   28

// d_out float32 layout (flattened tuple concat):
#define BASE_ROI 0
#define BASE_CLS (BB*TT*4)
#define BASE_DLT (BASE_CLS + BB*TT)
#define BASE_MSK (BASE_DLT + BB*TT*4)

typedef unsigned long long ull;

// Scratch (no device allocation allowed -> __device__ globals)
__device__ int   g_mask_mode;            // 0 = byte(bool/uint8), 1 = float32, 2 = int32
__device__ int   g_sel_ok[BB*PP];
__device__ int   g_sel_gt[BB*PP];
__device__ float g_sel_box[BB*PP*4];
__device__ float g_miou[BB*NN];
__device__ float g_cmax[BB*NN];
__device__ int   g_asn [BB*NN];

__device__ __forceinline__ unsigned int float_ord(float f) {
    unsigned int u = __float_as_uint(f);
    return (u & 0x80000000u) ? ~u : (u | 0x80000000u);
}
__device__ __forceinline__ ull umax64(ull a, ull b) { return a > b ? a : b; }
__device__ __forceinline__ ull umin64(ull a, ull b) { return a > b ? b : a; }

// ---------------------------------------------------------------------------
// Kernel A: IoU, warp-per-proposal, lanes over GT boxes. 32-bit reductions.
//   grid = (251, BB); block = 256 (8 warps = 8 proposals).
//   block (250, 0) -> mask dtype detection; (250, 1) -> noop.
// ---------------------------------------------------------------------------
__global__ void __launch_bounds__(256) iou_kernel(
    const float* __restrict__ props,   // (B,N,4)
    const int*   __restrict__ cls,     // (B,G)
    const float* __restrict__ boxes,   // (B,G,4)
    const void*  __restrict__ masks)
{
    if (blockIdx.x == 250) {
        if (blockIdx.y == 0 && threadIdx.x < 32) {
            const uint4* w4 = (const uint4*)masks;
            bool weird = false, sawF = false;
            for (int i = threadIdx.x; i < 512; i += 32) {   // 8KB sample
                uint4 v = w4[i];
                #define CHK(x) { unsigned int u = (x); \
                    if (u == 0x3F800000u) sawF = true; \
                    else if (u != 0u && u != 1u) weird = true; }
                CHK(v.x) CHK(v.y) CHK(v.z) CHK(v.w)
                #undef CHK
            }
            weird = __any_sync(0xFFFFFFFFu, weird);
            sawF  = __any_sync(0xFFFFFFFFu, sawF);
            if (threadIdx.x == 0) g_mask_mode = weird ? 0 : (sawF ? 1 : 2);
        }
        return;
    }

    const int b = blockIdx.y;
    const int t = threadIdx.x;
    const int lane = t & 31, w = t >> 5;
    const int n = blockIdx.x * 8 + w;          // 250*8 = 2000

    __shared__ float s_gt[GG*4];
    __shared__ int   s_cls[GG];
    for (int i = t; i < GG*4; i += 256) s_gt[i]  = boxes[b*GG*4 + i];
    for (int i = t; i < GG;   i += 256) s_cls[i] = cls[b*GG + i];
    __syncthreads();

    const float4 pb = ((const float4*)props)[b*NN + n];
    const float py1 = pb.x, px1 = pb.y, py2 = pb.z, px2 = pb.w;
    const float a1 = (py2 - py1) * (px2 - px1);

    float localov = -1.0f; int localg = 0; float cmax = -1.0f;
    #pragma unroll
    for (int g = lane; g < GG; g += 32) {
        float gy1 = s_gt[g*4+0], gx1 = s_gt[g*4+1];
        float gy2 = s_gt[g*4+2], gx2 = s_gt[g*4+3];
        float yy1 = fmaxf(py1, gy1), xx1 = fmaxf(px1, gx1);
        float yy2 = fminf(py2, gy2), xx2 = fminf(px2, gx2);
        float ih = fmaxf(yy2 - yy1, 0.0f);
        float iw = fmaxf(xx2 - xx1, 0.0f);
        float inter = ih * iw;
        float a2 = (gy2 - gy1) * (gx2 - gx1);
        float uni = a1 + a2 - inter;
        float iou = inter / fmaxf(uni, 1e-12f);
        bool crowd = (s_cls[g] < 0);
        float ov = crowd ? -1.0f : iou;
        if (ov > localov) { localov = ov; localg = g; }   // g ascending -> min-g tie
        cmax = fmaxf(cmax, crowd ? iou : -1.0f);
    }
    float wmax = localov;
    #pragma unroll
    for (int o = 16; o > 0; o >>= 1)
        wmax = fmaxf(wmax, __shfl_xor_sync(0xFFFFFFFFu, wmax, o));
    int cand = (localov == wmax) ? localg : 0x7FFFFFFF;
    #pragma unroll
    for (int o = 16; o > 0; o >>= 1) {
        cand = min(cand, __shfl_xor_sync(0xFFFFFFFFu, cand, o));
        cmax = fmaxf(cmax, __shfl_xor_sync(0xFFFFFFFFu, cmax, o));
    }
    if (lane == 0) {
        g_miou[b*NN + n] = wmax;
        g_asn [b*NN + n] = cand;
        g_cmax[b*NN + n] = cmax;
    }
}

// ---------------------------------------------------------------------------
// In-warp bitonic sort of 256 u64 keys held as k[8] per lane (elem = rr*32+lane),
// DESCENDING. Fully unrolled: j>=32 -> in-thread register CAS, j<32 -> shfl.
// ---------------------------------------------------------------------------
__device__ __forceinline__ void cas_pair(ull& a, ull& b, bool desc) {
    ull hi = umax64(a, b), lo = umin64(a, b);
    a = desc ? hi : lo;  b = desc ? lo : hi;
}

__device__ __forceinline__ void warp_sort256_desc(ull k[8], int lane) {
    #pragma unroll
    for (int kk = 2; kk <= 256; kk <<= 1) {
        #pragma unroll
        for (int j = kk >> 1; j >= 32; j >>= 1) {
            const int rj = j >> 5;
            #pragma unroll
            for (int rr = 0; rr < 8; rr++) if ((rr & rj) == 0) {
                bool desc = (((rr*32) & kk) == 0);   // kk>=64 here
                cas_pair(k[rr], k[rr | rj], desc);
            }
        }
        #pragma unroll
        for (int j = (kk >> 1) < 32 ? (kk >> 1) : 16; j >= 1; j >>= 1) {
            #pragma unroll
            for (int rr = 0; rr < 8; rr++) {
                ull p = __shfl_xor_sync(0xFFFFFFFFu, k[rr], j);
                bool desc = (((rr*32 + lane) & kk) == 0);
                bool up = ((lane & j) == 0);
                k[rr] = (up == desc) ? umax64(k[rr], p) : umin64(k[rr], p);
            }
        }
    }
}

// Input bitonic sequence in k[8] -> output DESC sorted.
__device__ __forceinline__ void warp_merge256_desc(ull k[8], int lane) {
    #pragma unroll
    for (int j = 128; j >= 32; j >>= 1) {
        const int rj = j >> 5;
        #pragma unroll
        for (int rr = 0; rr < 8; rr++) if ((rr & rj) == 0)
            cas_pair(k[rr], k[rr | rj], true);
    }
    #pragma unroll
    for (int j = 16; j >= 1; j >>= 1) {
        #pragma unroll
        for (int rr = 0; rr < 8; rr++) {
            ull p = __shfl_xor_sync(0xFFFFFFFFu, k[rr], j);
            bool up = ((lane & j) == 0);
            k[rr] = up ? umax64(k[rr], p) : umin64(k[rr], p);
        }
    }
}

// ---------------------------------------------------------------------------
// Kernel B: top-k select + output writes.
//   blocks 0..3: (image b = blk>>1, role = blk&1: 0=pos, 1=neg), 256 threads.
// 8 warps sort 256-key chunks in registers; 3-level top-256 merge tree
// (4 block barriers total). Keys unique -> exact jax.top_k order.
// ---------------------------------------------------------------------------
__global__ void __launch_bounds__(256) select_kernel(
    const float* __restrict__ props,   // (B,N,4)
    const int*   __restrict__ cls,     // (B,G)
    const float* __restrict__ boxes,   // (B,G,4)
    float*       __restrict__ out)
{
    const int b    = blockIdx.x >> 1;
    const int role = blockIdx.x & 1;          // 0 = positives, 1 = negatives
    const int t    = threadIdx.x;
    const int lane = t & 31, w = t >> 5;

    __shared__ ull sA[2048];
    __shared__ ull sB[1024];
    __shared__ ull sC[512];
    __shared__ ull sF[256];

    // Build this warp's 256 keys and sort in registers.
    ull k[8];
    #pragma unroll
    for (int rr = 0; rr < 8; rr++) {
        int n = w*256 + rr*32 + lane;
        ull key = 0ull;
        if (n < NN) {
            float v;
            if (role == 0) {
                float m = g_miou[b*NN + n];
                v = (m >= 0.5f) ? m : -1.0f;
            } else {
                float m = g_miou[b*NN + n];
                bool neg = (m < 0.5f) && (g_cmax[b*NN + n] < 0.001f);
                v = neg ? m : -1.0f;
            }
            key = ((ull)float_ord(v) << 32) |
                  (unsigned int)(0xFFFFFFFFu - (unsigned int)n);
        }
        k[rr] = key;
    }
    warp_sort256_desc(k, lane);
    #pragma unroll
    for (int rr = 0; rr < 8; rr++) sA[w*256 + rr*32 + lane] = k[rr];
    __syncthreads();

    // Level 1: 4 warps merge pairs of chunks -> top-256 each.
    if (w < 4) {
        #pragma unroll
        for (int rr = 0; rr < 8; rr++) {
            int e = rr*32 + lane;
            k[rr] = umax64(sA[w*512 + e], sA[w*512 + 256 + (255 - e)]);
        }
        warp_merge256_desc(k, lane);
        #pragma unroll
        for (int rr = 0; rr < 8; rr++) sB[w*256 + rr*32 + lane] = k[rr];
    }
    __syncthreads();

    // Level 2: 2 warps.
    if (w < 2) {
        #pragma unroll
        for (int rr = 0; rr < 8; rr++) {
            int e = rr*32 + lane;
            k[rr] = umax64(sB[w*512 + e], sB[w*512 + 256 + (255 - e)]);
        }
        warp_merge256_desc(k, lane);
        #pragma unroll
        for (int rr = 0; rr < 8; rr++) sC[w*256 + rr*32 + lane] = k[rr];
    }
    __syncthreads();

    // Level 3: 1 warp -> final top-256 descending.
    if (w == 0) {
        #pragma unroll
        for (int rr = 0; rr < 8; rr++) {
            int e = rr*32 + lane;
            k[rr] = umax64(sC[e], sC[256 + (255 - e)]);
        }
        warp_merge256_desc(k, lane);
        #pragma unroll
        for (int rr = 0; rr < 8; rr++) sF[rr*32 + lane] = k[rr];
    }
    __syncthreads();

    if (role == 0) {
        if (t < PP) {
            int i = t;
            int n = (int)(0xFFFFFFFFu - (unsigned int)sF[i]);
            float m = g_miou[b*NN + n];
            bool ok = (m >= 0.5f);
            int g = g_asn[b*NN + n];
            const float4 pb = ((const float4*)props)[b*NN + n];
            float q0 = pb.x, q1 = pb.y, q2 = pb.z, q3 = pb.w;
            int oT = b*TT + i;

            out[BASE_ROI + oT*4 + 0] = ok ? q0 : 0.0f;
            out[BASE_ROI + oT*4 + 1] = ok ? q1 : 0.0f;
            out[BASE_ROI + oT*4 + 2] = ok ? q2 : 0.0f;
            out[BASE_ROI + oT*4 + 3] = ok ? q3 : 0.0f;
            out[BASE_CLS + oT] = ok ? (float)cls[b*GG + g] : 0.0f;

            float d0=0.f, d1=0.f, d2=0.f, d3=0.f;
            if (ok) {
                float h  = q2 - q0, wd = q3 - q1;
                float cy = q0 + 0.5f*h, cx = q1 + 0.5f*wd;
                float gy1 = boxes[b*GG*4 + g*4+0], gx1 = boxes[b*GG*4 + g*4+1];
                float gy2 = boxes[b*GG*4 + g*4+2], gx2 = boxes[b*GG*4 + g*4+3];
                float gh = gy2 - gy1, gw = gx2 - gx1;
                float gcy = gy1 + 0.5f*gh, gcx = gx1 + 0.5f*gw;
                d0 = ((gcy - cy) / h) / 0.1f;
                d1 = ((gcx - cx) / wd) / 0.1f;
                d2 = logf(gh / h) / 0.2f;
                d3 = logf(gw / wd) / 0.2f;
            }
            out[BASE_DLT + oT*4 + 0] = d0;
            out[BASE_DLT + oT*4 + 1] = d1;
            out[BASE_DLT + oT*4 + 2] = d2;
            out[BASE_DLT + oT*4 + 3] = d3;

            int s = b*PP + i;
            g_sel_ok[s]      = ok ? 1 : 0;
            g_sel_gt[s]      = g;
            g_sel_box[s*4+0] = q0;
            g_sel_box[s*4+1] = q1;
            g_sel_box[s*4+2] = q2;
            g_sel_box[s*4+3] = q3;
        }
    } else {
        if (t < NEGN) {
            int i = t;
            int n = (int)(0xFFFFFFFFu - (unsigned int)sF[i]);
            float m = g_miou[b*NN + n];
            bool ok = (m < 0.5f) && (g_cmax[b*NN + n] < 0.001f);
            const float4 pb = ((const float4*)props)[b*NN + n];
            int oT = b*TT + PP + i;
            out[BASE_ROI + oT*4 + 0] = ok ? pb.x : 0.0f;
            out[BASE_ROI + oT*4 + 1] = ok ? pb.y : 0.0f;
            out[BASE_ROI + oT*4 + 2] = ok ? pb.z : 0.0f;
            out[BASE_ROI + oT*4 + 3] = ok ? pb.w : 0.0f;
            out[BASE_CLS + oT] = 0.0f;
            out[BASE_DLT + oT*4 + 0] = 0.0f;
            out[BASE_DLT + oT*4 + 1] = 0.0f;
            out[BASE_DLT + oT*4 + 2] = 0.0f;
            out[BASE_DLT + oT*4 + 3] = 0.0f;
        }
    }
}

// ---------------------------------------------------------------------------
// Kernel C: mask crop-resize. One block per (b,t), one THREAD per pixel.
// All float math via explicit rn intrinsics (no FMA contraction) to bit-match
// XLA's unfused mul/add sequence around the round() 0.5 knife edge.
// (VALIDATED bit-path — do not change the arithmetic.)
// ---------------------------------------------------------------------------
__device__ __forceinline__ float read_mask(const void* m, int mode, int b, int y, int x, int g) {
    size_t idx = (((size_t)b*HH + y)*WW + x)*GG + g;
    if (mode == 0) return ((const unsigned char*)m)[idx] ? 1.0f : 0.0f;
    if (mode == 1) return ((const float*)m)[idx];
    return (float)((const int*)m)[idx];
}

__global__ void __launch_bounds__(784) mask_kernel(const void* __restrict__ masks,
                                                   float* __restrict__ out)
{
    const int bt = blockIdx.x;
    const int b = bt / TT, t = bt % TT;
    float* mout = out + BASE_MSK + (size_t)bt * (MH*MW);
    const int i = threadIdx.x;           // 0..783, one pixel each

    if (t >= PP || !g_sel_ok[b*PP + t]) {
        mout[i] = 0.0f;
        return;
    }
    const int s = b*PP + t;
    const int g = g_sel_gt[s];
    const float by1 = g_sel_box[s*4+0], bx1 = g_sel_box[s*4+1];
    const float by2 = g_sel_box[s*4+2], bx2 = g_sel_box[s*4+3];
    const int mode = g_mask_mode;

    const float dy = __fsub_rn(by2, by1);
    const float dx = __fsub_rn(bx2, bx1);
    const float baseY = __fmul_rn(by1, (float)(HH-1));
    const float baseX = __fmul_rn(bx1, (float)(WW-1));

    int py = i / MW, px = i % MW;
    float ty = __fdiv_rn((float)py, (float)(MH-1));
    float ys = __fadd_rn(baseY, __fmul_rn(__fmul_rn(ty, dy), (float)(HH-1)));
    float tx = __fdiv_rn((float)px, (float)(MW-1));
    float xs = __fadd_rn(baseX, __fmul_rn(__fmul_rn(tx, dx), (float)(WW-1)));

    float y0f = floorf(ys), x0f = floorf(xs);
    float wy = __fsub_rn(ys, y0f);
    float wx = __fsub_rn(xs, x0f);
    int y0 = min(max((int)y0f, 0), HH-1);
    int y1 = min(y0 + 1, HH-1);
    int x0 = min(max((int)x0f, 0), WW-1);
    int x1 = min(x0 + 1, WW-1);

    float v00 = read_mask(masks, mode, b, y0, x0, g);
    float v01 = read_mask(masks, mode, b, y0, x1, g);
    float v10 = read_mask(masks, mode, b, y1, x0, g);
    float v11 = read_mask(masks, mode, b, y1, x1, g);

    float omwx = __fsub_rn(1.0f, wx);
    float omwy = __fsub_rn(1.0f, wy);
    float top = __fadd_rn(__fmul_rn(v00, omwx), __fmul_rn(v01, wx));
    float bot = __fadd_rn(__fmul_rn(v10, omwx), __fmul_rn(v11, wx));
    float v   = __fadd_rn(__fmul_rn(top, omwy), __fmul_rn(bot, wy));
    mout[i] = rintf(v);   // jnp.round = half-to-even
}

// ---------------------------------------------------------------------------
extern "C" void kernel_launch(void* const* d_in, const int* in_sizes, int n_in,
                              void* d_out, int out_size)
{
    const float* props = (const float*)d_in[0];   // (B,N,4)
    const int*   cls   = (const int*)  d_in[1];   // (B,G)
    const float* boxes = (const float*)d_in[2];   // (B,G,4)
    const void*  masks = d_in[3];                 // (B,H,W,G)

    float* out = (float*)d_out;

    dim3 gridA(251, BB);
    iou_kernel<<<gridA, 256>>>(props, cls, boxes, masks);
    select_kernel<<<4, 256>>>(props, cls, boxes, out);
    mask_kernel<<<BB*TT, 784>>>(masks, out);
}